// round 4
// baseline (speedup 1.0000x reference)
#include <cuda_runtime.h>
#include <cuda_bf16.h>
#include <cstdint>

#define B_SZ 4096
#define D_SZ 1024
#define EPS_F 1e-7f

#define BM 128
#define BN 256
#define NKB 16                       // 16 k-blocks of 64
#define A_TILE_B (BM * 64)           // 8192 B  (fp8, 128 rows x 64)
#define B_TILE_B (BN * 64)           // 16384 B (fp8, 256 rows x 64)
#define STAGE_B  (A_TILE_B + B_TILE_B)  // 24576 B
#define NSTAGE 8
#define SM_CTRL (NSTAGE * STAGE_B)   // 196608
#define DSMEM_TOTAL (SM_CTRL + 128)
#define NSM 152
#define NTILES 512                   // (4096/128) * (4096/256)

// ---- scratch (allocation-free rule: __device__ globals) -------------------
// Fragment-shuffled fp8 layouts:
// g_ln8: A frags [rb32][kb16][mf8][kf2] x 512B  (lane*16, regs a0..a3)
// g_rn8: B frags [nb16][kb16][nf32][kf2] x 256B (lane*8,  regs b0..b1)
__device__ __align__(1024) uint8_t g_ln8[B_SZ * D_SZ];
__device__ __align__(1024) uint8_t g_rn8[B_SZ * D_SZ];
__device__ float g_inv[2 * B_SZ];
__device__ float g_rowsum[B_SZ];
__device__ float g_colsum[B_SZ];
__device__ float g_diag[B_SZ];

// ---------------------------------------------------------------------------
__device__ __forceinline__ uint32_t smem_u32(const void* p) {
    uint32_t a;
    asm("{ .reg .u64 t; cvta.to.shared.u64 t, %1; cvt.u32.u64 %0, t; }"
        : "=r"(a) : "l"(p));
    return a;
}

__device__ __forceinline__ float fast_exp(float x) {
    float y = x * 1.4426950408889634f;
    float t = y + 12582912.0f;
    int   n = __float_as_int(t) - 0x4B400000;
    float f = y - (t - 12582912.0f);
    float p = 1.3333558e-3f;
    p = fmaf(p, f, 9.6181291e-3f);
    p = fmaf(p, f, 5.5504109e-2f);
    p = fmaf(p, f, 2.4022651e-1f);
    p = fmaf(p, f, 6.9314718e-1f);
    p = fmaf(p, f, 1.0f);
    return p * __int_as_float((n + 127) << 23);
}

// ---- mbarrier / bulk-copy helpers (plain sm_90 PTX) -----------------------
__device__ __forceinline__ void mb_init(uint32_t a, uint32_t cnt) {
    asm volatile("mbarrier.init.shared.b64 [%0], %1;" :: "r"(a), "r"(cnt) : "memory");
}
__device__ __forceinline__ void mb_expect(uint32_t a, uint32_t bytes) {
    asm volatile("mbarrier.arrive.expect_tx.shared.b64 _, [%0], %1;"
                 :: "r"(a), "r"(bytes) : "memory");
}
__device__ __forceinline__ void mb_arrive(uint32_t a) {
    asm volatile("mbarrier.arrive.shared.b64 _, [%0];" :: "r"(a) : "memory");
}
__device__ __forceinline__ void mb_wait(uint32_t a, uint32_t parity) {
    asm volatile(
        "{\n\t.reg .pred P;\n\t"
        "WL_%=:\n\t"
        "mbarrier.try_wait.parity.acquire.cta.shared::cta.b64 P, [%0], %1, 0x989680;\n\t"
        "@P bra.uni WD_%=;\n\t"
        "bra.uni WL_%=;\n\t"
        "WD_%=:\n\t}"
        :: "r"(a), "r"(parity) : "memory");
}
__device__ __forceinline__ void bulk_g2s(uint32_t dst, const void* src,
                                         uint32_t bytes, uint32_t mbar) {
    asm volatile(
        "cp.async.bulk.shared::cluster.global.mbarrier::complete_tx::bytes "
        "[%0], [%1], %2, [%3];"
        :: "r"(dst), "l"(src), "r"(bytes), "r"(mbar) : "memory");
}

// ---- fp8 mma --------------------------------------------------------------
__device__ __forceinline__ void qmma(float d[4], const uint4& a, const uint2& b) {
    asm volatile(
        "mma.sync.aligned.m16n8k32.row.col.f32.e4m3.e4m3.f32 "
        "{%0,%1,%2,%3}, {%4,%5,%6,%7}, {%8,%9}, {%0,%1,%2,%3};\n"
        : "+f"(d[0]), "+f"(d[1]), "+f"(d[2]), "+f"(d[3])
        : "r"(a.x), "r"(a.y), "r"(a.z), "r"(a.w), "r"(b.x), "r"(b.y));
}

// pack 4 scaled floats -> 4 e4m3 bytes, v.x in lowest byte
__device__ __forceinline__ uint32_t pack_e4m3(float4 v, float s) {
    uint16_t lo, hi;
    asm("cvt.rn.satfinite.e4m3x2.f32 %0, %1, %2;"
        : "=h"(lo) : "f"(v.y * s), "f"(v.x * s));
    asm("cvt.rn.satfinite.e4m3x2.f32 %0, %1, %2;"
        : "=h"(hi) : "f"(v.w * s), "f"(v.z * s));
    return (uint32_t)lo | ((uint32_t)hi << 16);
}

// ---------------------------------------------------------------------------
// Kernel 1a: row norms -> g_inv; zero stat arrays. warp per row.
// ---------------------------------------------------------------------------
__global__ void norm_kernel(const float* __restrict__ left,
                            const float* __restrict__ right) {
    int warp = threadIdx.x >> 5, lane = threadIdx.x & 31;
    int row = blockIdx.x * 8 + warp;          // 0..8191
    bool isL = row < B_SZ;
    int r = isL ? row : row - B_SZ;
    const float* src = (isL ? left : right) + (size_t)r * D_SZ;

    float ss = 0.0f;
    #pragma unroll
    for (int i = 0; i < 8; ++i) {
        float4 v = ((const float4*)src)[lane + 32 * i];
        ss += v.x * v.x + v.y * v.y + v.z * v.z + v.w * v.w;
    }
    #pragma unroll
    for (int o = 16; o > 0; o >>= 1) ss += __shfl_xor_sync(0xffffffffu, ss, o);
    if (lane == 0) {
        g_inv[row] = rsqrtf(fmaxf(ss, EPS_F));
        if (isL) { g_rowsum[r] = 0.0f; g_colsum[r] = 0.0f; }
    }
}

// ---------------------------------------------------------------------------
// Kernel 1b: scale + e4m3-quantize + fragment-shuffle layout.
// warp per fragment; A tasks [0,8192), B tasks [8192,24576).
// ---------------------------------------------------------------------------
__global__ void layout_kernel(const float* __restrict__ left,
                              const float* __restrict__ right) {
    int task = blockIdx.x * 8 + (threadIdx.x >> 5);
    int lane = threadIdx.x & 31;
    int lr = lane >> 2;            // 0..7
    int lk = (lane & 3) * 4;       // 0,4,8,12

    if (task < 8192) {             // A fragment: 16 rows x 32 k, 512B
        int rb = task >> 8;        // 0..31
        int kb = (task >> 4) & 15;
        int mf = (task >> 1) & 7;
        int kf = task & 1;
        int r0 = rb * 128 + mf * 16 + lr;
        int k0 = kb * 64 + kf * 32 + lk;
        float inv0 = g_inv[r0], inv1 = g_inv[r0 + 8];
        const float* s0 = left + (size_t)r0 * D_SZ + k0;
        const float* s1 = left + (size_t)(r0 + 8) * D_SZ + k0;
        uint4 out;
        out.x = pack_e4m3(*(const float4*)(s0),      inv0);   // a0
        out.y = pack_e4m3(*(const float4*)(s1),      inv1);   // a1
        out.z = pack_e4m3(*(const float4*)(s0 + 16), inv0);   // a2
        out.w = pack_e4m3(*(const float4*)(s1 + 16), inv1);   // a3
        *(uint4*)(g_ln8 + ((size_t)((rb * 16 + kb) * 16 + mf * 2 + kf)) * 512
                  + lane * 16) = out;
    } else {                       // B fragment: 8 n x 32 k, 256B
        int t = task - 8192;       // 0..16383
        int nb = t >> 10;          // 0..15
        int rem = t & 1023;
        int kb = rem >> 6;
        int nf = (rem >> 1) & 31;
        int kf = rem & 1;
        int n0 = nb * 256 + nf * 8 + lr;
        int k0 = kb * 64 + kf * 32 + lk;
        float inv0 = g_inv[B_SZ + n0];
        const float* s0 = right + (size_t)n0 * D_SZ + k0;
        uint2 out;
        out.x = pack_e4m3(*(const float4*)(s0),      inv0);   // b0
        out.y = pack_e4m3(*(const float4*)(s0 + 16), inv0);   // b1
        *(uint2*)(g_rn8 + ((size_t)((nb * 16 + kb) * 64 + nf * 2 + kf)) * 256
                  + lane * 8) = out;
    }
}

// ---------------------------------------------------------------------------
// Kernel 2: persistent fp8 GEMM, 128x256 tile, 512 thr (warps 2x8),
// 8-stage cp.async.bulk pipeline (full: tx, empty: 16 warp arrivals),
// fused exp / rowsum / colsum / diag epilogue per tile.
// ---------------------------------------------------------------------------
__device__ __forceinline__ void issue_load(uint32_t sbase, uint32_t mb_full,
                                           int g, int c) {
    int t = c + NSM * (g >> 4);
    int kb = g & 15;
    int bi = t >> 4, bj = t & 15;
    const uint8_t* A = g_ln8 + (size_t)(bi * 16 + kb) * A_TILE_B;
    const uint8_t* Bp = g_rn8 + (size_t)(bj * 16 + kb) * B_TILE_B;
    int s = g & 7;
    uint32_t dst = sbase + s * STAGE_B;
    mb_expect(mb_full + 8 * s, STAGE_B);
    bulk_g2s(dst, A, A_TILE_B, mb_full + 8 * s);
    bulk_g2s(dst + A_TILE_B, Bp, B_TILE_B, mb_full + 8 * s);
}

__global__ void __launch_bounds__(512, 1)
gemm_stats_kernel(const float* __restrict__ temperature) {
    extern __shared__ char dsm[];
    uint32_t sbase = smem_u32(dsm);
    const int tid = threadIdx.x, warp = tid >> 5, lane = tid & 31;
    const int c = blockIdx.x;
    const int NT = (NTILES - c + NSM - 1) / NSM;   // 3 or 4 tiles
    const int wr = warp >> 3;    // 0..1  (64-row slab)
    const int wc = warp & 7;     // 0..7  (32-col slab)
    const int grp = lane >> 2;   // 0..7
    const int qid = lane & 3;    // 0..3

    uint32_t mb_full  = sbase + SM_CTRL;        // 8 x 8B
    uint32_t mb_empty = sbase + SM_CTRL + 64;   // 8 x 8B

    if (tid == 0) {
        #pragma unroll
        for (int s = 0; s < NSTAGE; ++s) {
            mb_init(mb_full + 8 * s, 1);
            mb_init(mb_empty + 8 * s, 16);
        }
    }
    __syncthreads();

    if (tid == 0) {
        #pragma unroll
        for (int g = 0; g < NSTAGE; ++g) issue_load(sbase, mb_full, g, c);
    }

    const float scale = __expf(temperature[0]);
    const int GTOT = NT * 16;

    for (int ti = 0; ti < NT; ++ti) {
        int t = c + NSM * ti;
        int bi = t >> 4, bj = t & 15;

        float acc[4][4][4];
        #pragma unroll
        for (int mt = 0; mt < 4; ++mt)
            #pragma unroll
            for (int nt = 0; nt < 4; ++nt)
                #pragma unroll
                for (int k = 0; k < 4; ++k) acc[mt][nt][k] = 0.0f;

        for (int kb = 0; kb < 16; ++kb) {
            int g = ti * 16 + kb;
            int s = g & 7;
            int par = (g >> 3) & 1;
            mb_wait(mb_full + 8 * s, par);

            const char* stg = dsm + s * STAGE_B;
            #pragma unroll
            for (int kf = 0; kf < 2; ++kf) {
                uint4 af[4];
                uint2 bf[4];
                #pragma unroll
                for (int mt = 0; mt < 4; ++mt)
                    af[mt] = *(const uint4*)(stg
                        + ((wr * 4 + mt) * 2 + kf) * 512 + lane * 16);
                #pragma unroll
                for (int nt = 0; nt < 4; ++nt)
                    bf[nt] = *(const uint2*)(stg + A_TILE_B
                        + ((wc * 4 + nt) * 2 + kf) * 256 + lane * 8);
                #pragma unroll
                for (int mt = 0; mt < 4; ++mt)
                    #pragma unroll
                    for (int nt = 0; nt < 4; ++nt)
                        qmma(acc[mt][nt], af[mt], bf[nt]);
            }
            __syncwarp();
            if (lane == 0) mb_arrive(mb_empty + 8 * s);
            if (tid == 0) {
                int g2 = g + NSTAGE;
                if (g2 < GTOT) {
                    mb_wait(mb_empty + 8 * s, par);  // all 16 warps done with s
                    issue_load(sbase, mb_full, g2, c);
                }
            }
        }

        // ---- per-tile epilogue ----
        #pragma unroll
        for (int mt = 0; mt < 4; ++mt)
            #pragma unroll
            for (int nt = 0; nt < 4; ++nt)
                #pragma unroll
                for (int k = 0; k < 4; ++k)
                    acc[mt][nt][k] = fast_exp(fmaf(acc[mt][nt][k], scale, -scale));

        // row sums
        #pragma unroll
        for (int mt = 0; mt < 4; ++mt) {
            float s0 = 0.0f, s1 = 0.0f;
            #pragma unroll
            for (int nt = 0; nt < 4; ++nt) {
                s0 += acc[mt][nt][0] + acc[mt][nt][1];
                s1 += acc[mt][nt][2] + acc[mt][nt][3];
            }
            s0 += __shfl_xor_sync(0xffffffffu, s0, 1);
            s0 += __shfl_xor_sync(0xffffffffu, s0, 2);
            s1 += __shfl_xor_sync(0xffffffffu, s1, 1);
            s1 += __shfl_xor_sync(0xffffffffu, s1, 2);
            if (qid == 0) {
                int row = bi * BM + wr * 64 + mt * 16 + grp;
                atomicAdd(&g_rowsum[row], s0);
                atomicAdd(&g_rowsum[row + 8], s1);
            }
        }

        // col sums
        #pragma unroll
        for (int nt = 0; nt < 4; ++nt) {
            float t0 = 0.0f, t1 = 0.0f;
            #pragma unroll
            for (int mt = 0; mt < 4; ++mt) {
                t0 += acc[mt][nt][0] + acc[mt][nt][2];
                t1 += acc[mt][nt][1] + acc[mt][nt][3];
            }
            t0 += __shfl_xor_sync(0xffffffffu, t0, 4);
            t0 += __shfl_xor_sync(0xffffffffu, t0, 8);
            t0 += __shfl_xor_sync(0xffffffffu, t0, 16);
            t1 += __shfl_xor_sync(0xffffffffu, t1, 4);
            t1 += __shfl_xor_sync(0xffffffffu, t1, 8);
            t1 += __shfl_xor_sync(0xffffffffu, t1, 16);
            if (grp == 0) {
                int col = bj * BN + wc * 32 + nt * 8 + 2 * qid;
                atomicAdd(&g_colsum[col], t0);
                atomicAdd(&g_colsum[col + 1], t1);
            }
        }

        // diagonal (CTA intersects diagonal when bi>>1 == bj)
        if ((bi >> 1) == bj) {
            int doff = (bi & 1) * 128;
            #pragma unroll
            for (int mt = 0; mt < 4; ++mt) {
                int lrow = wr * 64 + mt * 16 + grp;
                #pragma unroll
                for (int nt = 0; nt < 4; ++nt) {
                    int lcol = wc * 32 + nt * 8 + 2 * qid;
                    if (lcol == lrow + doff)         g_diag[bi * BM + lrow]     = acc[mt][nt][0];
                    if (lcol + 1 == lrow + doff)     g_diag[bi * BM + lrow]     = acc[mt][nt][1];
                    if (lcol == lrow + 8 + doff)     g_diag[bi * BM + lrow + 8] = acc[mt][nt][2];
                    if (lcol + 1 == lrow + 8 + doff) g_diag[bi * BM + lrow + 8] = acc[mt][nt][3];
                }
            }
        }
    }
}

// ---------------------------------------------------------------------------
// Kernel 3: traces -> closed-form loss
// ---------------------------------------------------------------------------
__global__ void finalize_kernel(float* __restrict__ out) {
    int tid = threadIdx.x;
    float tl = 0.0f, tr = 0.0f;
    for (int i = tid; i < B_SZ; i += 256) {
        float d = g_diag[i];
        tl += d / g_rowsum[i];
        tr += d / g_colsum[i];
    }
    #pragma unroll
    for (int o = 16; o > 0; o >>= 1) {
        tl += __shfl_xor_sync(0xffffffffu, tl, o);
        tr += __shfl_xor_sync(0xffffffffu, tr, o);
    }
    __shared__ float sl[8], sr[8];
    if ((tid & 31) == 0) { sl[tid >> 5] = tl; sr[tid >> 5] = tr; }
    __syncthreads();
    if (tid == 0) {
        float TL = 0.0f, TR = 0.0f;
        #pragma unroll
        for (int w = 0; w < 8; ++w) { TL += sl[w]; TR += sr[w]; }
        float logeps = logf(EPS_F);
        float log1m  = logf(1.0f - EPS_F);
        float ll = -(TL * log1m + ((float)B_SZ - TL) * logeps);
        float lr = -(TR * log1m + ((float)B_SZ - TR) * logeps);
        out[0] = (ll + lr) * 0.5f / (float)B_SZ;
    }
}

// ---------------------------------------------------------------------------
extern "C" void kernel_launch(void* const* d_in, const int* in_sizes, int n_in,
                              void* d_out, int out_size) {
    const float* left  = (const float*)d_in[0];
    const float* right = (const float*)d_in[1];
    const float* temp  = (const float*)d_in[2];

    static bool attr_set = false;
    if (!attr_set) {
        cudaFuncSetAttribute(gemm_stats_kernel,
                             cudaFuncAttributeMaxDynamicSharedMemorySize,
                             DSMEM_TOTAL);
        attr_set = true;
    }

    norm_kernel<<<1024, 256>>>(left, right);
    layout_kernel<<<3072, 256>>>(left, right);
    gemm_stats_kernel<<<NSM, 512, DSMEM_TOTAL>>>(temp);
    finalize_kernel<<<1, 256>>>((float*)d_out);
}